// round 4
// baseline (speedup 1.0000x reference)
#include <cuda_runtime.h>
#include <math.h>
#include <stdint.h>

#define N_TOK 4096      // B*T
#define DDIM  1024
#define HDIM  4096
#define NEXP  8
#define NSLOT (N_TOK * 2)

// ---------------- scratch (static device globals; no cudaMalloc) ----------
__device__ float g_h[(size_t)NSLOT * HDIM];          // 128 MB (tf32-rounded)
__device__ float g_eo[(size_t)NSLOT * DDIM];         //  32 MB (full fp32)
__device__ float g_xr[(size_t)N_TOK * DDIM];         //  16 MB (tf32-rounded x)
__device__ float g_w1t[(size_t)NEXP * DDIM * HDIM];  // 128 MB : [E][H][D] rounded
__device__ float g_w2t[(size_t)NEXP * DDIM * HDIM];  // 128 MB : [E][D][H] rounded
__device__ int   g_perm[NSLOT];
__device__ int   g_slot_of[NSLOT];
__device__ int   g_tope[NSLOT];
__device__ float g_topw[NSLOT];
__device__ int   g_cnt[NEXP];
__device__ int   g_off[NEXP];
__device__ int   g_cur[NEXP];

// ======================= PTX helpers (compute_103-safe) ====================
__device__ __forceinline__ uint32_t smem_u32(const void* p) {
    uint32_t a;
    asm("{ .reg .u64 t; cvta.to.shared.u64 t, %1; cvt.u32.u64 %0, t; }"
        : "=r"(a) : "l"(p));
    return a;
}
__device__ __forceinline__ void cp_async16(uint32_t dst, const void* src, uint32_t sz) {
    asm volatile("cp.async.ca.shared.global [%0], [%1], 16, %2;"
                 :: "r"(dst), "l"(src), "r"(sz) : "memory");
}
#define CP_COMMIT() asm volatile("cp.async.commit_group;" ::: "memory")
#define CP_WAIT(n)  asm volatile("cp.async.wait_group %0;" :: "n"(n) : "memory")

__device__ __forceinline__ void ldsm_x4(uint32_t* r, uint32_t addr) {
    asm volatile("ldmatrix.sync.aligned.m8n8.x4.shared.b16 {%0,%1,%2,%3}, [%4];"
                 : "=r"(r[0]), "=r"(r[1]), "=r"(r[2]), "=r"(r[3]) : "r"(addr));
}
__device__ __forceinline__ float to_tf32f(float x) {
    uint32_t o;
    asm("cvt.rna.tf32.f32 %0, %1;" : "=r"(o) : "f"(x));
    return __uint_as_float(o);
}
__device__ __forceinline__ void mma_tf32(float* d, const uint32_t* a,
                                         uint32_t b0, uint32_t b1) {
    asm volatile(
        "mma.sync.aligned.m16n8k8.row.col.f32.tf32.tf32.f32 "
        "{%0,%1,%2,%3}, {%4,%5,%6,%7}, {%8,%9}, {%0,%1,%2,%3};"
        : "+f"(d[0]), "+f"(d[1]), "+f"(d[2]), "+f"(d[3])
        : "r"(a[0]), "r"(a[1]), "r"(a[2]), "r"(a[3]), "r"(b0), "r"(b1));
}

// ======================= small kernels ======================================
__global__ void reset_kernel() {
    int i = threadIdx.x;
    if (i < NEXP) { g_cnt[i] = 0; g_cur[i] = 0; }
}

__global__ void gate_kernel(const float* __restrict__ x,
                            const float* __restrict__ Wg,
                            const float* __restrict__ bg) {
    int t = blockIdx.x;
    int lane = threadIdx.x;
    const float* xr = x + (size_t)t * DDIM;
    float p[NEXP];
#pragma unroll
    for (int e = 0; e < NEXP; e++) p[e] = 0.f;
    for (int d = lane; d < DDIM; d += 32) {
        float xv = xr[d];
        const float4* w4 = reinterpret_cast<const float4*>(Wg + (size_t)d * NEXP);
        float4 a = w4[0], b = w4[1];
        p[0] += xv * a.x; p[1] += xv * a.y; p[2] += xv * a.z; p[3] += xv * a.w;
        p[4] += xv * b.x; p[5] += xv * b.y; p[6] += xv * b.z; p[7] += xv * b.w;
    }
#pragma unroll
    for (int off = 16; off; off >>= 1)
#pragma unroll
        for (int e = 0; e < NEXP; e++)
            p[e] += __shfl_xor_sync(0xffffffffu, p[e], off);
    if (lane == 0) {
#pragma unroll
        for (int e = 0; e < NEXP; e++) p[e] += bg[e];
        int i0 = 0;
#pragma unroll
        for (int e = 1; e < NEXP; e++) if (p[e] > p[i0]) i0 = e;
        int i1 = (i0 == 0) ? 1 : 0;
#pragma unroll
        for (int e = 0; e < NEXP; e++)
            if (e != i0 && p[e] > p[i1]) i1 = e;
        float e1 = expf(p[i1] - p[i0]);
        float w0 = 1.0f / (1.0f + e1);
        float w1 = e1 / (1.0f + e1);
        g_tope[t * 2 + 0] = i0;  g_tope[t * 2 + 1] = i1;
        g_topw[t * 2 + 0] = w0;  g_topw[t * 2 + 1] = w1;
        atomicAdd(&g_cnt[i0], 1);
        atomicAdd(&g_cnt[i1], 1);
    }
}

__global__ void offsets_kernel() {
    if (threadIdx.x == 0) {
        int acc = 0;
        for (int e = 0; e < NEXP; e++) { g_off[e] = acc; acc += g_cnt[e]; }
    }
}

__global__ void scatter_kernel() {
    int t = blockIdx.x * blockDim.x + threadIdx.x;
    if (t >= N_TOK) return;
#pragma unroll
    for (int k = 0; k < 2; k++) {
        int e = g_tope[t * 2 + k];
        int pos = g_off[e] + atomicAdd(&g_cur[e], 1);
        g_perm[pos] = t;
        g_slot_of[t * 2 + k] = pos;
    }
}

// ---------------- x -> tf32-rounded copy -----------------------------------
__global__ void round_x_kernel(const float* __restrict__ x, float* __restrict__ xr) {
    int i = blockIdx.x * blockDim.x + threadIdx.x;
    const float4* in = reinterpret_cast<const float4*>(x);
    float4* out = reinterpret_cast<float4*>(xr);
    float4 v = in[i];
    out[i] = make_float4(to_tf32f(v.x), to_tf32f(v.y), to_tf32f(v.z), to_tf32f(v.w));
}

// ---------------- weight transpose+round: in [R][C] -> out [C][R] ----------
__global__ void transpose_round_kernel(const float* __restrict__ in,
                                       float* __restrict__ out, int R, int C) {
    __shared__ float t[32][33];
    const float* ine = in + (size_t)blockIdx.z * R * C;
    float* oute = out + (size_t)blockIdx.z * R * C;
    int x = blockIdx.x * 32 + threadIdx.x;
    int y0 = blockIdx.y * 32 + threadIdx.y;
#pragma unroll
    for (int j = 0; j < 32; j += 8)
        t[threadIdx.y + j][threadIdx.x] = ine[(size_t)(y0 + j) * C + x];
    __syncthreads();
    int x2 = blockIdx.y * 32 + threadIdx.x;
    int y2 = blockIdx.x * 32 + threadIdx.y;
#pragma unroll
    for (int j = 0; j < 32; j += 8)
        oute[(size_t)(y2 + j) * R + x2] = to_tf32f(t[threadIdx.x][threadIdx.y + j]);
}

// ======================= tf32 mma.sync grouped GEMM =========================
// CTA tile 128(M) x 256(N), k-chunk 32, 8 warps (2m x 4n), warp tile 64x64.
// A smem: [128 m][32 k], B smem: [256 n][32 k]; both 128B rows with
// 16B-granule XOR swizzle; ALL fragments via ldmatrix (data pre-rounded tf32).
// 3-stage cp.async pipeline.
#define ASTAGE_B 16384
#define BSTAGE_B 32768
#define OFF_A    1024
#define OFF_B    (OFF_A + 3 * ASTAGE_B)           // 50176
#define SM_BYTES (OFF_B + 3 * BSTAGE_B)           // 148480

template <int KDIM, bool GATHER, bool DOGELU, bool ROUNDOUT>
__global__ __launch_bounds__(256) void moe_gemm(
    const float* __restrict__ Asrc, const float* __restrict__ BT,
    const float* __restrict__ bias, float* __restrict__ Out, int Ntot) {
    extern __shared__ char smem[];
    const int e = blockIdx.z;
    const int cnt = g_cnt[e];
    const int m0 = blockIdx.x * 128;
    if (m0 >= cnt) return;
    const int off = g_off[e];
    const int n0 = blockIdx.y * 256;
    const float* Bte = BT + (size_t)e * Ntot * KDIM;   // [Ntot][KDIM]

    const uint32_t sb = smem_u32(smem);
    const int tid = threadIdx.x;
    const int wid = tid >> 5, lane = tid & 31;
    const int wm = wid & 1, wn = wid >> 1;
    const int m_base = wm * 64, n_base = wn * 64;

    int* rowtok = (int*)smem;
    if (GATHER && tid < 128) {
        int r = m0 + tid;
        rowtok[tid] = (r < cnt) ? g_perm[off + r] : -1;
    }
    __syncthreads();

    constexpr int NC = KDIM / 32;

    auto load_chunk = [&](int c) {
        const int s = c % 3;
        const int k0 = c * 32;
        const uint32_t Abs = sb + OFF_A + s * ASTAGE_B;
        const uint32_t Bbs = sb + OFF_B + s * BSTAGE_B;
        // A: 128 rows x 8 granules
#pragma unroll
        for (int f = 0; f < 4; f++) {
            int id = tid + f * 256;
            int row = id >> 3, g = id & 7;
            uint32_t sz = 16;
            const char* src;
            if (GATHER) {
                int tok = rowtok[row];
                if (tok < 0) { sz = 0; tok = 0; }
                src = (const char*)(Asrc + (size_t)tok * KDIM + k0) + g * 16;
            } else {
                int mr = m0 + row;
                if (mr >= cnt) { sz = 0; mr = 0; }
                src = (const char*)(Asrc + (size_t)(off + mr) * KDIM + k0) + g * 16;
            }
            cp_async16(Abs + row * 128 + ((g ^ (row & 7)) << 4), src, sz);
        }
        // B: 256 rows x 8 granules
#pragma unroll
        for (int f = 0; f < 8; f++) {
            int id = tid + f * 256;
            int row = id >> 3, g = id & 7;
            const char* src =
                (const char*)(Bte + (size_t)(n0 + row) * KDIM + k0) + g * 16;
            cp_async16(Bbs + row * 128 + ((g ^ (row & 7)) << 4), src, 16);
        }
        CP_COMMIT();
    };

    float acc[4][8][4];
#pragma unroll
    for (int mi = 0; mi < 4; mi++)
#pragma unroll
        for (int ni = 0; ni < 8; ni++)
#pragma unroll
            for (int q = 0; q < 4; q++) acc[mi][ni][q] = 0.f;

    load_chunk(0);
    load_chunk(1);

    const int rowsel = ((lane >> 3) & 1) * 8 + (lane & 7);
    const int gsel = (lane >> 4);

#pragma unroll 1
    for (int c = 0; c < NC; c++) {
        if (c + 2 < NC) { load_chunk(c + 2); CP_WAIT(2); }
        else if (c + 1 < NC) { CP_WAIT(1); }
        else { CP_WAIT(0); }
        __syncthreads();
        const int s = c % 3;
        const uint32_t Abs = sb + OFF_A + s * ASTAGE_B;
        const uint32_t Bbs = sb + OFF_B + s * BSTAGE_B;
#pragma unroll
        for (int ks = 0; ks < 4; ks++) {
            const int g = ks * 2 + gsel;
            uint32_t a[4][4];
#pragma unroll
            for (int mi = 0; mi < 4; mi++) {
                int row = m_base + mi * 16 + rowsel;
                ldsm_x4(a[mi], Abs + row * 128 + ((g ^ (row & 7)) << 4));
            }
            uint32_t b[4][4];
#pragma unroll
            for (int q = 0; q < 4; q++) {
                int row = n_base + q * 16 + rowsel;
                ldsm_x4(b[q], Bbs + row * 128 + ((g ^ (row & 7)) << 4));
            }
#pragma unroll
            for (int mi = 0; mi < 4; mi++)
#pragma unroll
                for (int q = 0; q < 4; q++) {
                    mma_tf32(acc[mi][2 * q + 0], a[mi], b[q][0], b[q][2]);
                    mma_tf32(acc[mi][2 * q + 1], a[mi], b[q][1], b[q][3]);
                }
        }
        __syncthreads();
    }

    // ---- epilogue: bias (+gelu) (+tf32 round) + store ----
    const int lr = lane >> 2;
    const int lc = (lane & 3) * 2;
    float2 bv[8];
#pragma unroll
    for (int ni = 0; ni < 8; ni++) {
        int col = n0 + n_base + ni * 8 + lc;
        const float* bp = bias + (size_t)e * Ntot + col;
        bv[ni] = make_float2(bp[0], bp[1]);
    }
#pragma unroll
    for (int mi = 0; mi < 4; mi++) {
        int r0 = m0 + m_base + mi * 16 + lr;
        int r1 = r0 + 8;
        bool v0 = r0 < cnt, v1 = r1 < cnt;
        float* o0 = Out + (size_t)(off + r0) * Ntot + n0 + n_base + lc;
        float* o1 = Out + (size_t)(off + r1) * Ntot + n0 + n_base + lc;
#pragma unroll
        for (int ni = 0; ni < 8; ni++) {
            if (v0) {
                float x0 = acc[mi][ni][0] + bv[ni].x;
                float x1 = acc[mi][ni][1] + bv[ni].y;
                if (DOGELU) { x0 = x0 * normcdff(x0); x1 = x1 * normcdff(x1); }
                if (ROUNDOUT) { x0 = to_tf32f(x0); x1 = to_tf32f(x1); }
                *reinterpret_cast<float2*>(o0 + ni * 8) = make_float2(x0, x1);
            }
            if (v1) {
                float x2 = acc[mi][ni][2] + bv[ni].x;
                float x3 = acc[mi][ni][3] + bv[ni].y;
                if (DOGELU) { x2 = x2 * normcdff(x2); x3 = x3 * normcdff(x3); }
                if (ROUNDOUT) { x2 = to_tf32f(x2); x3 = to_tf32f(x3); }
                *reinterpret_cast<float2*>(o1 + ni * 8) = make_float2(x2, x3);
            }
        }
    }
}

// ---------------- combine: out[t] = w0*eo[s0] + w1*eo[s1] ------------------
__global__ void combine_kernel(float* __restrict__ out) {
    int t = blockIdx.x;
    int s0 = g_slot_of[t * 2 + 0], s1 = g_slot_of[t * 2 + 1];
    float w0 = g_topw[t * 2 + 0], w1 = g_topw[t * 2 + 1];
    const float4* a = reinterpret_cast<const float4*>(g_eo + (size_t)s0 * DDIM);
    const float4* b = reinterpret_cast<const float4*>(g_eo + (size_t)s1 * DDIM);
    float4* o = reinterpret_cast<float4*>(out + (size_t)t * DDIM);
    for (int i = threadIdx.x; i < DDIM / 4; i += blockDim.x) {
        float4 va = a[i], vb = b[i];
        o[i] = make_float4(w0 * va.x + w1 * vb.x, w0 * va.y + w1 * vb.y,
                           w0 * va.z + w1 * vb.z, w0 * va.w + w1 * vb.w);
    }
}

// ---------------- launch ----------------------------------------------------
extern "C" void kernel_launch(void* const* d_in, const int* in_sizes, int n_in,
                              void* d_out, int out_size) {
    const float* x  = (const float*)d_in[0];
    const float* Wg = (const float*)d_in[1];
    const float* bg = (const float*)d_in[2];
    const float* W1 = (const float*)d_in[3];
    const float* b1 = (const float*)d_in[4];
    const float* W2 = (const float*)d_in[5];
    const float* b2 = (const float*)d_in[6];
    float* out = (float*)d_out;

    void *p_h, *p_eo, *p_xr, *p_w1t, *p_w2t;
    cudaGetSymbolAddress(&p_h,   g_h);
    cudaGetSymbolAddress(&p_eo,  g_eo);
    cudaGetSymbolAddress(&p_xr,  g_xr);
    cudaGetSymbolAddress(&p_w1t, g_w1t);
    cudaGetSymbolAddress(&p_w2t, g_w2t);

    cudaFuncSetAttribute(moe_gemm<DDIM, true,  true,  true>,
                         cudaFuncAttributeMaxDynamicSharedMemorySize, SM_BYTES);
    cudaFuncSetAttribute(moe_gemm<HDIM, false, false, false>,
                         cudaFuncAttributeMaxDynamicSharedMemorySize, SM_BYTES);

    reset_kernel<<<1, 32>>>();
    gate_kernel<<<N_TOK, 32>>>(x, Wg, bg);
    offsets_kernel<<<1, 32>>>();
    scatter_kernel<<<(N_TOK + 255) / 256, 256>>>();
    round_x_kernel<<<(N_TOK * DDIM / 4) / 256, 256>>>(x, (float*)p_xr);
    // W1 [E][1024][4096] -> [E][4096][1024] (rounded)
    transpose_round_kernel<<<dim3(128, 32, NEXP), dim3(32, 8)>>>(
        W1, (float*)p_w1t, 1024, 4096);
    // W2 [E][4096][1024] -> [E][1024][4096] (rounded)
    transpose_round_kernel<<<dim3(32, 128, NEXP), dim3(32, 8)>>>(
        W2, (float*)p_w2t, 4096, 1024);
    // GEMM1: h = round(gelu(x[perm] @ W1 + b1))  K=1024, N=4096
    moe_gemm<DDIM, true, true, true><<<dim3(32, HDIM / 256, NEXP), 256, SM_BYTES>>>(
        (const float*)p_xr, (const float*)p_w1t, b1, (float*)p_h, HDIM);
    // GEMM2: eo = h @ W2 + b2                    K=4096, N=1024
    moe_gemm<HDIM, false, false, false><<<dim3(32, DDIM / 256, NEXP), 256, SM_BYTES>>>(
        (const float*)p_h, (const float*)p_w2t, b2, (float*)p_eo, DDIM);
    combine_kernel<<<N_TOK, 256>>>(out);
}

// round 5
// speedup vs baseline: 1.7120x; 1.7120x over previous
#include <cuda_runtime.h>
#include <cuda_fp16.h>
#include <math.h>
#include <stdint.h>

#define N_TOK 4096      // B*T
#define DDIM  1024
#define HDIM  4096
#define NEXP  8
#define NSLOT (N_TOK * 2)

// ---------------- scratch (static device globals; no cudaMalloc) ----------
__device__ __half g_hh[(size_t)NSLOT * HDIM];         // 64 MB : gelu out (fp16)
__device__ float  g_eo[(size_t)NSLOT * DDIM];         // 32 MB : expert out (fp32)
__device__ __half g_xh[(size_t)N_TOK * DDIM];         //  8 MB : x (fp16)
__device__ __half g_w1h[(size_t)NEXP * DDIM * HDIM];  // 64 MB : W1 [E][D][H] fp16
__device__ __half g_w2h[(size_t)NEXP * DDIM * HDIM];  // 64 MB : W2 [E][H][D] fp16
__device__ int   g_perm[NSLOT];
__device__ int   g_slot_of[NSLOT];
__device__ int   g_tope[NSLOT];
__device__ float g_topw[NSLOT];
__device__ int   g_cnt[NEXP];
__device__ int   g_off[NEXP];
__device__ int   g_cur[NEXP];

// ======================= PTX helpers (compute_103-safe) ====================
__device__ __forceinline__ uint32_t smem_u32(const void* p) {
    uint32_t a;
    asm("{ .reg .u64 t; cvta.to.shared.u64 t, %1; cvt.u32.u64 %0, t; }"
        : "=r"(a) : "l"(p));
    return a;
}
__device__ __forceinline__ void cp_async16(uint32_t dst, const void* src, uint32_t sz) {
    asm volatile("cp.async.ca.shared.global [%0], [%1], 16, %2;"
                 :: "r"(dst), "l"(src), "r"(sz) : "memory");
}
#define CP_COMMIT() asm volatile("cp.async.commit_group;" ::: "memory")
#define CP_WAIT(n)  asm volatile("cp.async.wait_group %0;" :: "n"(n) : "memory")

__device__ __forceinline__ void ldsm_x4(uint32_t* r, uint32_t addr) {
    asm volatile("ldmatrix.sync.aligned.m8n8.x4.shared.b16 {%0,%1,%2,%3}, [%4];"
                 : "=r"(r[0]), "=r"(r[1]), "=r"(r[2]), "=r"(r[3]) : "r"(addr));
}
__device__ __forceinline__ void ldsm_x4_t(uint32_t* r, uint32_t addr) {
    asm volatile("ldmatrix.sync.aligned.m8n8.x4.trans.shared.b16 {%0,%1,%2,%3}, [%4];"
                 : "=r"(r[0]), "=r"(r[1]), "=r"(r[2]), "=r"(r[3]) : "r"(addr));
}
__device__ __forceinline__ void mma_f16(float* d, const uint32_t* a,
                                        uint32_t b0, uint32_t b1) {
    asm volatile(
        "mma.sync.aligned.m16n8k16.row.col.f32.f16.f16.f32 "
        "{%0,%1,%2,%3}, {%4,%5,%6,%7}, {%8,%9}, {%0,%1,%2,%3};"
        : "+f"(d[0]), "+f"(d[1]), "+f"(d[2]), "+f"(d[3])
        : "r"(a[0]), "r"(a[1]), "r"(a[2]), "r"(a[3]), "r"(b0), "r"(b1));
}

// ======================= small kernels ======================================
__global__ void reset_kernel() {
    int i = threadIdx.x;
    if (i < NEXP) { g_cnt[i] = 0; g_cur[i] = 0; }
}

__global__ void gate_kernel(const float* __restrict__ x,
                            const float* __restrict__ Wg,
                            const float* __restrict__ bg) {
    int t = blockIdx.x;
    int lane = threadIdx.x;
    const float* xr = x + (size_t)t * DDIM;
    float p[NEXP];
#pragma unroll
    for (int e = 0; e < NEXP; e++) p[e] = 0.f;
    for (int d = lane; d < DDIM; d += 32) {
        float xv = xr[d];
        const float4* w4 = reinterpret_cast<const float4*>(Wg + (size_t)d * NEXP);
        float4 a = w4[0], b = w4[1];
        p[0] += xv * a.x; p[1] += xv * a.y; p[2] += xv * a.z; p[3] += xv * a.w;
        p[4] += xv * b.x; p[5] += xv * b.y; p[6] += xv * b.z; p[7] += xv * b.w;
    }
#pragma unroll
    for (int off = 16; off; off >>= 1)
#pragma unroll
        for (int e = 0; e < NEXP; e++)
            p[e] += __shfl_xor_sync(0xffffffffu, p[e], off);
    if (lane == 0) {
#pragma unroll
        for (int e = 0; e < NEXP; e++) p[e] += bg[e];
        int i0 = 0;
#pragma unroll
        for (int e = 1; e < NEXP; e++) if (p[e] > p[i0]) i0 = e;
        int i1 = (i0 == 0) ? 1 : 0;
#pragma unroll
        for (int e = 0; e < NEXP; e++)
            if (e != i0 && p[e] > p[i1]) i1 = e;
        float e1 = expf(p[i1] - p[i0]);
        float w0 = 1.0f / (1.0f + e1);
        float w1 = e1 / (1.0f + e1);
        g_tope[t * 2 + 0] = i0;  g_tope[t * 2 + 1] = i1;
        g_topw[t * 2 + 0] = w0;  g_topw[t * 2 + 1] = w1;
        atomicAdd(&g_cnt[i0], 1);
        atomicAdd(&g_cnt[i1], 1);
    }
}

__global__ void offsets_kernel() {
    if (threadIdx.x == 0) {
        int acc = 0;
        for (int e = 0; e < NEXP; e++) { g_off[e] = acc; acc += g_cnt[e]; }
    }
}

__global__ void scatter_kernel() {
    int t = blockIdx.x * blockDim.x + threadIdx.x;
    if (t >= N_TOK) return;
#pragma unroll
    for (int k = 0; k < 2; k++) {
        int e = g_tope[t * 2 + k];
        int pos = g_off[e] + atomicAdd(&g_cur[e], 1);
        g_perm[pos] = t;
        g_slot_of[t * 2 + k] = pos;
    }
}

// ---------------- fp32 -> fp16 elementwise (8 elems/thread) ----------------
__global__ void conv_half_kernel(const float* __restrict__ in,
                                 __half* __restrict__ out) {
    size_t i = (size_t)(blockIdx.x * blockDim.x + threadIdx.x) * 8;
    float4 v0 = *reinterpret_cast<const float4*>(in + i);
    float4 v1 = *reinterpret_cast<const float4*>(in + i + 4);
    __half2 h[4];
    h[0] = __floats2half2_rn(v0.x, v0.y);
    h[1] = __floats2half2_rn(v0.z, v0.w);
    h[2] = __floats2half2_rn(v1.x, v1.y);
    h[3] = __floats2half2_rn(v1.z, v1.w);
    *reinterpret_cast<uint4*>(out + i) = *reinterpret_cast<uint4*>(h);
}

// ======================= fp16 mma.sync grouped GEMM =========================
// CTA tile 128(M) x 256(N), k-chunk 64 (halves), 8 warps (2m x 4n),
// warp tile 64x64, m16n8k16 HMMA fp32 accum.
// A smem: [128 m][64 k] halves (128B rows), XOR-granule swizzle, ldmatrix.x4.
// B smem: [64 k][256 n] halves (512B rows), XOR-granule swizzle, ldmatrix.x4.trans.
// 3-stage cp.async pipeline.
#define ASTAGE_B 16384
#define BSTAGE_B 32768
#define OFF_A    1024
#define OFF_B    (OFF_A + 3 * ASTAGE_B)
#define SM_BYTES (OFF_B + 3 * BSTAGE_B)   // 148480

template <int KDIM, bool GATHER, bool DOGELU, typename OutT>
__global__ __launch_bounds__(256) void moe_gemm(
    const __half* __restrict__ Ah, const __half* __restrict__ Bh,
    const float* __restrict__ bias, OutT* __restrict__ Out, int Ntot) {
    extern __shared__ char smem[];
    const int e = blockIdx.z;
    const int cnt = g_cnt[e];
    const int m0 = blockIdx.x * 128;
    if (m0 >= cnt) return;
    const int off = g_off[e];
    const int n0 = blockIdx.y * 256;
    const __half* Bte = Bh + (size_t)e * KDIM * Ntot;   // [K][Ntot]

    const uint32_t sb = smem_u32(smem);
    const int tid = threadIdx.x;
    const int wid = tid >> 5, lane = tid & 31;
    const int wm = wid & 1, wn = wid >> 1;
    const int m_base = wm * 64, n_base = wn * 64;

    int* rowtok = (int*)smem;
    if (GATHER && tid < 128) {
        int r = m0 + tid;
        rowtok[tid] = (r < cnt) ? g_perm[off + r] : -1;
    }
    __syncthreads();

    constexpr int NC = KDIM / 64;

    auto load_chunk = [&](int c) {
        const int s = c % 3;
        const int k0 = c * 64;                     // in halves
        const uint32_t Abs = sb + OFF_A + s * ASTAGE_B;
        const uint32_t Bbs = sb + OFF_B + s * BSTAGE_B;
        // A: 128 rows x 8 granules (16B = 8 halves)
#pragma unroll
        for (int f = 0; f < 4; f++) {
            int id = tid + f * 256;
            int row = id >> 3, g = id & 7;
            uint32_t sz = 16;
            const char* src;
            if (GATHER) {
                int tok = rowtok[row];
                if (tok < 0) { sz = 0; tok = 0; }
                src = (const char*)(Ah + (size_t)tok * KDIM + k0) + g * 16;
            } else {
                int mr = m0 + row;
                if (mr >= cnt) { sz = 0; mr = 0; }
                src = (const char*)(Ah + (size_t)(off + mr) * KDIM + k0) + g * 16;
            }
            cp_async16(Abs + row * 128 + ((g ^ (row & 7)) << 4), src, sz);
        }
        // B: 64 k-rows x 32 granules
#pragma unroll
        for (int f = 0; f < 8; f++) {
            int id = tid + f * 256;
            int krow = id >> 5, g = id & 31;
            const char* src =
                (const char*)(Bte + (size_t)(k0 + krow) * Ntot + n0) + g * 16;
            cp_async16(Bbs + krow * 512 + ((g ^ (krow & 7)) << 4), src, 16);
        }
        CP_COMMIT();
    };

    float acc[4][8][4];
#pragma unroll
    for (int mi = 0; mi < 4; mi++)
#pragma unroll
        for (int ni = 0; ni < 8; ni++)
#pragma unroll
            for (int q = 0; q < 4; q++) acc[mi][ni][q] = 0.f;

    load_chunk(0);
    load_chunk(1);

    const int rowsel = ((lane >> 3) & 1) * 8 + (lane & 7);   // A: row-in-16
    const int gsel = (lane >> 4);                            // A: granule select
    const int bksel = lane & 15;                             // B: k-row-in-16
    const int bgsel = lane >> 4;                             // B: n-granule select

#pragma unroll 1
    for (int c = 0; c < NC; c++) {
        if (c + 2 < NC) { load_chunk(c + 2); CP_WAIT(2); }
        else if (c + 1 < NC) { CP_WAIT(1); }
        else { CP_WAIT(0); }
        __syncthreads();
        const int s = c % 3;
        const uint32_t Abs = sb + OFF_A + s * ASTAGE_B;
        const uint32_t Bbs = sb + OFF_B + s * BSTAGE_B;
#pragma unroll
        for (int ks = 0; ks < 4; ks++) {
            // A fragments: 4 m16 tiles
            const int ga = ks * 2 + gsel;
            uint32_t a[4][4];
#pragma unroll
            for (int mi = 0; mi < 4; mi++) {
                int row = m_base + mi * 16 + rowsel;
                ldsm_x4(a[mi], Abs + row * 128 + ((ga ^ (row & 7)) << 4));
            }
            // B fragments: 4 n16 tiles via ldmatrix.trans
            const int krow = ks * 16 + bksel;
            uint32_t b[4][4];
#pragma unroll
            for (int nq = 0; nq < 4; nq++) {
                int g = wn * 8 + nq * 2 + bgsel;
                ldsm_x4_t(b[nq], Bbs + krow * 512 + ((g ^ (krow & 7)) << 4));
            }
#pragma unroll
            for (int mi = 0; mi < 4; mi++)
#pragma unroll
                for (int nq = 0; nq < 4; nq++) {
                    mma_f16(acc[mi][2 * nq + 0], a[mi], b[nq][0], b[nq][1]);
                    mma_f16(acc[mi][2 * nq + 1], a[mi], b[nq][2], b[nq][3]);
                }
        }
        __syncthreads();
    }

    // ---- epilogue: bias (+gelu) + store ----
    const int lr = lane >> 2;
    const int lc = (lane & 3) * 2;
    float2 bv[8];
#pragma unroll
    for (int ni = 0; ni < 8; ni++) {
        int col = n0 + n_base + ni * 8 + lc;
        const float* bp = bias + (size_t)e * Ntot + col;
        bv[ni] = make_float2(bp[0], bp[1]);
    }
#pragma unroll
    for (int mi = 0; mi < 4; mi++) {
        int r0 = m0 + m_base + mi * 16 + lr;
        int r1 = r0 + 8;
        bool v0 = r0 < cnt, v1 = r1 < cnt;
        OutT* o0 = Out + (size_t)(off + r0) * Ntot + n0 + n_base + lc;
        OutT* o1 = Out + (size_t)(off + r1) * Ntot + n0 + n_base + lc;
#pragma unroll
        for (int ni = 0; ni < 8; ni++) {
            if (v0) {
                float x0 = acc[mi][ni][0] + bv[ni].x;
                float x1 = acc[mi][ni][1] + bv[ni].y;
                if (DOGELU) { x0 = x0 * normcdff(x0); x1 = x1 * normcdff(x1); }
                if (sizeof(OutT) == 2)
                    *reinterpret_cast<__half2*>(o0 + ni * 8) = __floats2half2_rn(x0, x1);
                else
                    *reinterpret_cast<float2*>(o0 + ni * 8) = make_float2(x0, x1);
            }
            if (v1) {
                float x2 = acc[mi][ni][2] + bv[ni].x;
                float x3 = acc[mi][ni][3] + bv[ni].y;
                if (DOGELU) { x2 = x2 * normcdff(x2); x3 = x3 * normcdff(x3); }
                if (sizeof(OutT) == 2)
                    *reinterpret_cast<__half2*>(o1 + ni * 8) = __floats2half2_rn(x2, x3);
                else
                    *reinterpret_cast<float2*>(o1 + ni * 8) = make_float2(x2, x3);
            }
        }
    }
}

// ---------------- combine: out[t] = w0*eo[s0] + w1*eo[s1] ------------------
__global__ void combine_kernel(float* __restrict__ out) {
    int t = blockIdx.x;
    int s0 = g_slot_of[t * 2 + 0], s1 = g_slot_of[t * 2 + 1];
    float w0 = g_topw[t * 2 + 0], w1 = g_topw[t * 2 + 1];
    const float4* a = reinterpret_cast<const float4*>(g_eo + (size_t)s0 * DDIM);
    const float4* b = reinterpret_cast<const float4*>(g_eo + (size_t)s1 * DDIM);
    float4* o = reinterpret_cast<float4*>(out + (size_t)t * DDIM);
    for (int i = threadIdx.x; i < DDIM / 4; i += blockDim.x) {
        float4 va = a[i], vb = b[i];
        o[i] = make_float4(w0 * va.x + w1 * vb.x, w0 * va.y + w1 * vb.y,
                           w0 * va.z + w1 * vb.z, w0 * va.w + w1 * vb.w);
    }
}

// ---------------- launch ----------------------------------------------------
extern "C" void kernel_launch(void* const* d_in, const int* in_sizes, int n_in,
                              void* d_out, int out_size) {
    const float* x  = (const float*)d_in[0];
    const float* Wg = (const float*)d_in[1];
    const float* bg = (const float*)d_in[2];
    const float* W1 = (const float*)d_in[3];
    const float* b1 = (const float*)d_in[4];
    const float* W2 = (const float*)d_in[5];
    const float* b2 = (const float*)d_in[6];
    float* out = (float*)d_out;

    void *p_hh, *p_eo, *p_xh, *p_w1h, *p_w2h;
    cudaGetSymbolAddress(&p_hh,  g_hh);
    cudaGetSymbolAddress(&p_eo,  g_eo);
    cudaGetSymbolAddress(&p_xh,  g_xh);
    cudaGetSymbolAddress(&p_w1h, g_w1h);
    cudaGetSymbolAddress(&p_w2h, g_w2h);

    cudaFuncSetAttribute(moe_gemm<DDIM, true,  true,  __half>,
                         cudaFuncAttributeMaxDynamicSharedMemorySize, SM_BYTES);
    cudaFuncSetAttribute(moe_gemm<HDIM, false, false, float>,
                         cudaFuncAttributeMaxDynamicSharedMemorySize, SM_BYTES);

    reset_kernel<<<1, 32>>>();
    gate_kernel<<<N_TOK, 32>>>(x, Wg, bg);
    offsets_kernel<<<1, 32>>>();
    scatter_kernel<<<(N_TOK + 255) / 256, 256>>>();
    // fp32 -> fp16 conversions
    conv_half_kernel<<<((size_t)N_TOK * DDIM / 8) / 256, 256>>>(x, (__half*)p_xh);
    conv_half_kernel<<<((size_t)NEXP * DDIM * HDIM / 8) / 256, 256>>>(W1, (__half*)p_w1h);
    conv_half_kernel<<<((size_t)NEXP * DDIM * HDIM / 8) / 256, 256>>>(W2, (__half*)p_w2h);
    // GEMM1: h = fp16(gelu(x[perm] @ W1 + b1))   K=1024, N=4096
    moe_gemm<DDIM, true, true, __half>
        <<<dim3(32, HDIM / 256, NEXP), 256, SM_BYTES>>>(
        (const __half*)p_xh, (const __half*)p_w1h, b1, (__half*)p_hh, HDIM);
    // GEMM2: eo = h @ W2 + b2                    K=4096, N=1024
    moe_gemm<HDIM, false, false, float>
        <<<dim3(32, DDIM / 256, NEXP), 256, SM_BYTES>>>(
        (const __half*)p_hh, (const __half*)p_w2h, b2, (float*)p_eo, DDIM);
    combine_kernel<<<N_TOK, 256>>>(out);
}